// round 6
// baseline (speedup 1.0000x reference)
#include <cuda_runtime.h>
#include <cuda_bf16.h>
#include <cstdint>

// Problem constants
#define BB 8
#define LL 2048
#define DD 512
#define RR 512
#define M1 (BB * LL)   // 16384 flattened (B,L)

typedef __nv_bfloat16 bf16;
typedef __nv_bfloat162 bf162;

__device__ __forceinline__ uint32_t smem_to_u32(const void* smem_ptr) {
    uint32_t addr;
    asm("{ .reg .u64 tmp; cvta.to.shared.u64 tmp, %1; cvt.u32.u64 %0, tmp; }"
        : "=r"(addr) : "l"(smem_ptr));
    return addr;
}

__device__ __forceinline__ void bf16split(float x, bf16& h, bf16& l) {
    h = __float2bfloat16(x);
    l = __float2bfloat16(x - __bfloat162float(h));
}

#define CPASYNC16(dst, src) \
    asm volatile("cp.async.cg.shared.global [%0], [%1], 16;" :: "r"(dst), "l"(src))
#define CPASYNC_COMMIT() asm volatile("cp.async.commit_group;" ::: "memory")

#define LDSM4(r0, r1, r2, r3, addr) \
    asm volatile("ldmatrix.sync.aligned.m8n8.x4.shared.b16 {%0,%1,%2,%3}, [%4];" \
                 : "=r"(r0), "=r"(r1), "=r"(r2), "=r"(r3) : "r"(addr))

#define MMA16816(c, a, b) \
    asm volatile("mma.sync.aligned.m16n8k16.row.col.f32.bf16.bf16.f32 " \
                 "{%0,%1,%2,%3}, {%4,%5,%6,%7}, {%8,%9}, {%0,%1,%2,%3};" \
                 : "+f"((c)[0]), "+f"((c)[1]), "+f"((c)[2]), "+f"((c)[3]) \
                 : "r"((a)[0]), "r"((a)[1]), "r"((a)[2]), "r"((a)[3]), \
                   "r"((b)[0]), "r"((b)[1]))

// ---------------- scratch (device globals; no allocation allowed) ----------
__device__ bf16  g_query_h[(size_t)M1 * DD];
__device__ bf16  g_query_l[(size_t)M1 * DD];
__device__ bf16  g_wq_h[DD * DD];
__device__ bf16  g_wq_l[DD * DD];
__device__ bf16  g_wc_h[RR * LL];
__device__ bf16  g_wc_l[RR * LL];
__device__ bf16  g_qT_h[(size_t)BB * DD * LL];
__device__ bf16  g_qT_l[(size_t)BB * DD * LL];
__device__ bf16  g_qcat_h[(size_t)M1 * 1024];   // [q^2 | q]
__device__ bf16  g_qcat_l[(size_t)M1 * 1024];
__device__ bf16  g_bcat_h[RR * 1024];           // [invw2 | -2c*invw2]
__device__ bf16  g_bcat_l[RR * 1024];
__device__ float g_z[(size_t)M1 * RR];
__device__ bf16  g_fss_h[(size_t)M1 * RR];
__device__ bf16  g_fss_l[(size_t)M1 * RR];
__device__ bf16  g_conqT_h[(size_t)BB * DD * RR];
__device__ bf16  g_conqT_l[(size_t)BB * DD * RR];
__device__ float g_cc[RR];

// ---------------------------------------------------------------------------
// split: fp32 -> (hi, lo) bf16 (for Wq, Wc)
// ---------------------------------------------------------------------------
__global__ void split_kernel(const float* __restrict__ src, bf16* __restrict__ hi,
                             bf16* __restrict__ lo, int n4) {
    int i = blockIdx.x * blockDim.x + threadIdx.x;
    if (i >= n4) return;
    float4 v = ((const float4*)src)[i];
    bf16 h0, l0, h1, l1, h2, l2, h3, l3;
    bf16split(v.x, h0, l0); bf16split(v.y, h1, l1);
    bf16split(v.z, h2, l2); bf16split(v.w, h3, l3);
    bf162 hh0; hh0.x = h0; hh0.y = h1;
    bf162 hh1; hh1.x = h2; hh1.y = h3;
    bf162 ll0; ll0.x = l0; ll0.y = l1;
    bf162 ll1; ll1.x = l2; ll1.y = l3;
    ((bf162*)hi)[i * 2 + 0] = hh0;
    ((bf162*)hi)[i * 2 + 1] = hh1;
    ((bf162*)lo)[i * 2 + 0] = ll0;
    ((bf162*)lo)[i * 2 + 1] = ll1;
}

// ---------------------------------------------------------------------------
// query prep: single read of query -> row-major split AND transposed split
// ---------------------------------------------------------------------------
__global__ void query_prep_kernel(const float* __restrict__ query) {
    __shared__ float tile[32][33];
    int b = blockIdx.z;
    int l0 = blockIdx.x * 32, d0 = blockIdx.y * 32;
    int tx = threadIdx.x, ty = threadIdx.y;
    const float* src = query + (size_t)b * LL * DD;
#pragma unroll
    for (int i = 0; i < 4; i++) {
        int l = l0 + ty + 8 * i;
        float v = src[(size_t)l * DD + d0 + tx];
        tile[ty + 8 * i][tx] = v;
        bf16 h, lw;
        bf16split(v, h, lw);
        size_t idx = (size_t)(b * LL + l) * DD + d0 + tx;
        g_query_h[idx] = h;
        g_query_l[idx] = lw;
    }
    __syncthreads();
    size_t base = (size_t)b * DD * LL;
#pragma unroll
    for (int i = 0; i < 4; i++) {
        float v = tile[tx][ty + 8 * i];
        bf16 h, lw;
        bf16split(v, h, lw);
        size_t idx = base + (size_t)(d0 + ty + 8 * i) * LL + l0 + tx;
        g_qT_h[idx] = h;
        g_qT_l[idx] = lw;
    }
}

// ---------------------------------------------------------------------------
// prep: bcat = [invw2 | -2c*invw2] split, cc[r] = sum c^2*invw2
// ---------------------------------------------------------------------------
__global__ void prep_kernel(const float* __restrict__ centers,
                            const float* __restrict__ widths) {
    int r = blockIdx.x;
    int t = threadIdx.x;  // 128
    float acc = 0.f;
    for (int d = t; d < DD; d += 128) {
        float w = widths[r * DD + d];
        float c = centers[r * DD + d];
        float iw = 1.0f / (w * w);
        float b2 = -2.0f * c * iw;
        bf16 h, l;
        bf16split(iw, h, l);
        g_bcat_h[r * 1024 + d] = h;
        g_bcat_l[r * 1024 + d] = l;
        bf16split(b2, h, l);
        g_bcat_h[r * 1024 + 512 + d] = h;
        g_bcat_l[r * 1024 + 512 + d] = l;
        acc += c * c * iw;
    }
    __shared__ float sred[128];
    sred[t] = acc;
    __syncthreads();
    for (int s = 64; s > 0; s >>= 1) {
        if (t < s) sred[t] += sred[t + s];
        __syncthreads();
    }
    if (t == 0) g_cc[r] = sred[0];
}

// ---------------------------------------------------------------------------
// bf16-split NT GEMM via mma.sync m16n8k16, 3 passes (AhBh + AhBl + AlBh).
// 128x128 CTA tile, 8 warps of 64x32. K-chunk 32, 3-stage cp.async pipeline.
// SMEM tile: 128 rows x 64B, XOR-swizzled (col16 ^= (row>>1)&3), 8KB/tile.
// Epilogue: stage fp32 C in smem (pitch 132), then coalesced mode-writes.
// MODE 0: qcat ((v+aux)^2 | (v+aux), split; ldc=1024)
// MODE 1: fp32 scale*(v+aux[n]) -> Cf
// MODE 2: split bf16 v+aux[n]   -> Ch/Cl
// MODE 3: fp32 raw              -> Cf
// ---------------------------------------------------------------------------
#define TILE_B 8192                  // 128 rows x 64B
#define STAGE_B (4 * TILE_B)         // Ah, Al, Bh, Bl = 32KB
#define CS_PITCH 132
#define GEMM_SMEM (3 * STAGE_B)      // 98304 >= 128*132*4 = 67584

template <int MODE>
__global__ __launch_bounds__(256, 1) void gemm_bf16s(
    const bf16* __restrict__ Ah, const bf16* __restrict__ Al, int lda, size_t sA,
    const bf16* __restrict__ Bh, const bf16* __restrict__ Bl, int ldb, size_t sB,
    float* __restrict__ Cf, bf16* __restrict__ Ch, bf16* __restrict__ Cl,
    int ldc, size_t sC, const float* __restrict__ aux, int K) {
    extern __shared__ char smem[];
    uint32_t sb = smem_to_u32(smem);
    int t = threadIdx.x;
    int lane = t & 31, wid = t >> 5;
    int wm = wid & 1, wn = wid >> 1;
    int bn = blockIdx.x * 128, bm = blockIdx.y * 128;
    size_t bz = blockIdx.z;
    Ah += bz * sA; Al += bz * sA;
    Bh += bz * sB; Bl += bz * sB;

    // per-thread cp.async plan: 8 x 16B per chunk (512 transfers / 4 tiles)
    const bf16* gp[8];
    uint32_t so[8];
#pragma unroll
    for (int tl = 0; tl < 4; tl++) {
#pragma unroll
        for (int i = 0; i < 2; i++) {
            int idx = t + i * 256;           // 0..511
            int row = idx >> 2;              // 0..127
            int c = idx & 3;                 // 16B column
            const bf16* src;
            if (tl == 0)      src = Ah + (size_t)(bm + row) * lda;
            else if (tl == 1) src = Al + (size_t)(bm + row) * lda;
            else if (tl == 2) src = Bh + (size_t)(bn + row) * ldb;
            else              src = Bl + (size_t)(bn + row) * ldb;
            gp[tl * 2 + i] = src + c * 8;
            so[tl * 2 + i] = tl * TILE_B + row * 64 + ((c ^ ((row >> 1) & 3)) * 16);
        }
    }

    float acc[4][4][4] = {};
    const int nk = K >> 5;

    // prologue: chunks 0,1 -> stages 0,1
#pragma unroll
    for (int u = 0; u < 8; u++) CPASYNC16(sb + so[u], gp[u]);
    CPASYNC_COMMIT();
#pragma unroll
    for (int u = 0; u < 8; u++) CPASYNC16(sb + STAGE_B + so[u], gp[u] + 32);
    CPASYNC_COMMIT();

    int lm = lane & 15, lq = lane >> 4;
    int arow = wm * 64 + lm;
    int brow = wn * 32 + lm;
    uint32_t asw = (uint32_t)((arow >> 1) & 3);
    uint32_t bsw = (uint32_t)((brow >> 1) & 3);
    // (row + 16i) keeps (row>>1)&3 invariant, so swizzle term is per-thread const
    uint32_t a_base = (uint32_t)arow * 64;
    uint32_t b_base = (uint32_t)brow * 64;

    for (int kt = 0; kt < nk; kt++) {
        if (kt + 1 < nk) {
            asm volatile("cp.async.wait_group 1;" ::: "memory");
        } else {
            asm volatile("cp.async.wait_group 0;" ::: "memory");
        }
        __syncthreads();
        if (kt + 2 < nk) {
            uint32_t db = sb + ((kt + 2) % 3) * STAGE_B;
            int koff = (kt + 2) * 32;
#pragma unroll
            for (int u = 0; u < 8; u++) CPASYNC16(db + so[u], gp[u] + koff);
            CPASYNC_COMMIT();
        }
        uint32_t base = sb + (kt % 3) * STAGE_B;
#pragma unroll
        for (int ks = 0; ks < 2; ks++) {
            uint32_t kcol = (uint32_t)(ks * 2);     // 16B-col base {0,2}
            uint32_t aco = ((lq | kcol) ^ asw) * 16;
            uint32_t bco = ((lq | kcol) ^ bsw) * 16;
            uint32_t a[4][4], bh[4][2], bl[4][2];
#pragma unroll
            for (int i = 0; i < 4; i++)
                LDSM4(a[i][0], a[i][1], a[i][2], a[i][3],
                      base + a_base + i * (16 * 64) + aco);
#pragma unroll
            for (int jj = 0; jj < 2; jj++) {
                uint32_t r0, r1, r2, r3;
                LDSM4(r0, r1, r2, r3,
                      base + 2 * TILE_B + b_base + jj * (16 * 64) + bco);
                bh[2 * jj][0] = r0; bh[2 * jj][1] = r2;
                bh[2 * jj + 1][0] = r1; bh[2 * jj + 1][1] = r3;
            }
#pragma unroll
            for (int i = 0; i < 4; i++)
#pragma unroll
                for (int j = 0; j < 4; j++) MMA16816(acc[i][j], a[i], bh[j]);
#pragma unroll
            for (int jj = 0; jj < 2; jj++) {
                uint32_t r0, r1, r2, r3;
                LDSM4(r0, r1, r2, r3,
                      base + 3 * TILE_B + b_base + jj * (16 * 64) + bco);
                bl[2 * jj][0] = r0; bl[2 * jj][1] = r2;
                bl[2 * jj + 1][0] = r1; bl[2 * jj + 1][1] = r3;
            }
#pragma unroll
            for (int i = 0; i < 4; i++)
#pragma unroll
                for (int j = 0; j < 4; j++) MMA16816(acc[i][j], a[i], bl[j]);
#pragma unroll
            for (int i = 0; i < 4; i++)
                LDSM4(a[i][0], a[i][1], a[i][2], a[i][3],
                      base + TILE_B + a_base + i * (16 * 64) + aco);
#pragma unroll
            for (int i = 0; i < 4; i++)
#pragma unroll
                for (int j = 0; j < 4; j++) MMA16816(acc[i][j], a[i], bh[j]);
        }
        __syncthreads();
    }

    // ---- epilogue: stage fp32 C tile in smem, then coalesced writes ----
    float* Cs = (float*)smem;
    {
        int rb = wm * 64 + (lane >> 2);
        int nb = wn * 32 + (lane & 3) * 2;
#pragma unroll
        for (int i = 0; i < 4; i++)
#pragma unroll
            for (int h = 0; h < 2; h++) {
                int row = rb + i * 16 + h * 8;
#pragma unroll
                for (int j = 0; j < 4; j++) {
                    float2 v;
                    v.x = acc[i][j][2 * h];
                    v.y = acc[i][j][2 * h + 1];
                    *(float2*)(Cs + row * CS_PITCH + nb + j * 8) = v;
                }
            }
    }
    __syncthreads();

    if (MODE == 1 || MODE == 3) {
        const float scale = -0.5f / (float)DD;
#pragma unroll
        for (int it = 0; it < 16; it++) {
            int idx = t + it * 256;          // 0..4095
            int row = idx >> 5;
            int c4 = (idx & 31) * 4;
            const float* p = Cs + row * CS_PITCH + c4;
            float4 v = {p[0], p[1], p[2], p[3]};
            if (MODE == 1) {
                v.x = scale * (v.x + aux[bn + c4 + 0]);
                v.y = scale * (v.y + aux[bn + c4 + 1]);
                v.z = scale * (v.z + aux[bn + c4 + 2]);
                v.w = scale * (v.w + aux[bn + c4 + 3]);
            }
            *(float4*)(Cf + bz * sC + (size_t)(bm + row) * ldc + bn + c4) = v;
        }
    } else {
        int row = t >> 1;
        int cb = (t & 1) * 64;
        const float* p = Cs + row * CS_PITCH + cb;
        if (MODE == 0) {
            size_t crow = (size_t)(bm + row) * 1024 + bn + cb;
#pragma unroll
            for (int j = 0; j < 64; j += 2) {
                float q0 = p[j] + aux[bn + cb + j];
                float q1 = p[j + 1] + aux[bn + cb + j + 1];
                bf16 h0, l0, h1, l1;
                bf16split(q0 * q0, h0, l0); bf16split(q1 * q1, h1, l1);
                bf162 hh; hh.x = h0; hh.y = h1;
                bf162 ll; ll.x = l0; ll.y = l1;
                *(bf162*)(g_qcat_h + crow + j) = hh;
                *(bf162*)(g_qcat_l + crow + j) = ll;
                bf16split(q0, h0, l0); bf16split(q1, h1, l1);
                hh.x = h0; hh.y = h1; ll.x = l0; ll.y = l1;
                *(bf162*)(g_qcat_h + crow + 512 + j) = hh;
                *(bf162*)(g_qcat_l + crow + 512 + j) = ll;
            }
        } else {  // MODE 2
            size_t crow = bz * sC + (size_t)(bm + row) * ldc + bn + cb;
#pragma unroll
            for (int j = 0; j < 64; j += 2) {
                float q0 = p[j] + aux[bn + cb + j];
                float q1 = p[j + 1] + aux[bn + cb + j + 1];
                bf16 h0, l0, h1, l1;
                bf16split(q0, h0, l0); bf16split(q1, h1, l1);
                bf162 hh; hh.x = h0; hh.y = h1;
                bf162 ll; ll.x = l0; ll.y = l1;
                *(bf162*)(Ch + crow + j) = hh;
                *(bf162*)(Cl + crow + j) = ll;
            }
        }
    }
}

// ---------------------------------------------------------------------------
// softmax over R: reads fp32 g_z (scaled logits), writes split Fss
// ---------------------------------------------------------------------------
__global__ void softmax_kernel() {
    int row = blockIdx.x;
    int t = threadIdx.x;  // 256
    const float* zrow = g_z + (size_t)row * RR;
    float v0 = zrow[t];
    float v1 = zrow[t + 256];
    float m = fmaxf(v0, v1);
#pragma unroll
    for (int o = 16; o > 0; o >>= 1) m = fmaxf(m, __shfl_xor_sync(0xffffffffu, m, o));
    __shared__ float sm[8];
    __shared__ float ss[8];
    int wid = t >> 5, lid = t & 31;
    if (lid == 0) sm[wid] = m;
    __syncthreads();
    float mm = sm[0];
#pragma unroll
    for (int i = 1; i < 8; i++) mm = fmaxf(mm, sm[i]);
    float e0 = __expf(v0 - mm), e1 = __expf(v1 - mm);
    float s = e0 + e1;
#pragma unroll
    for (int o = 16; o > 0; o >>= 1) s += __shfl_xor_sync(0xffffffffu, s, o);
    if (lid == 0) ss[wid] = s;
    __syncthreads();
    float tot = 0.f;
#pragma unroll
    for (int i = 0; i < 8; i++) tot += ss[i];
    float inv = 1.0f / tot;
    size_t i0 = (size_t)row * RR + t;
    size_t i1 = i0 + 256;
    bf16 h, l;
    bf16split(e0 * inv, h, l);
    g_fss_h[i0] = h; g_fss_l[i0] = l;
    bf16split(e1 * inv, h, l);
    g_fss_h[i1] = h; g_fss_l[i1] = l;
}

// ---------------------------------------------------------------------------
extern "C" void kernel_launch(void* const* d_in, const int* in_sizes, int n_in,
                              void* d_out, int out_size) {
    const float* query   = (const float*)d_in[0];   // (B,L,D)
    const float* Wq      = (const float*)d_in[1];   // (D,D)
    const float* bq      = (const float*)d_in[2];   // (D,)
    const float* Wc      = (const float*)d_in[3];   // (R,L)
    const float* bc      = (const float*)d_in[4];   // (R,)
    const float* centers = (const float*)d_in[5];   // (R,D)
    const float* widths  = (const float*)d_in[6];   // (R,D)
    float* out = (float*)d_out;                     // (B,L,D)

    cudaFuncSetAttribute(gemm_bf16s<0>, cudaFuncAttributeMaxDynamicSharedMemorySize, GEMM_SMEM);
    cudaFuncSetAttribute(gemm_bf16s<1>, cudaFuncAttributeMaxDynamicSharedMemorySize, GEMM_SMEM);
    cudaFuncSetAttribute(gemm_bf16s<2>, cudaFuncAttributeMaxDynamicSharedMemorySize, GEMM_SMEM);
    cudaFuncSetAttribute(gemm_bf16s<3>, cudaFuncAttributeMaxDynamicSharedMemorySize, GEMM_SMEM);

    bf16 *qh, *ql, *wqh, *wql, *wch, *wcl, *qTh, *qTl, *qch, *qcl;
    bf16 *bch_, *bcl_, *fh, *fl, *cth, *ctl;
    float *zp, *ccp;
    cudaGetSymbolAddress((void**)&qh, g_query_h);
    cudaGetSymbolAddress((void**)&ql, g_query_l);
    cudaGetSymbolAddress((void**)&wqh, g_wq_h);
    cudaGetSymbolAddress((void**)&wql, g_wq_l);
    cudaGetSymbolAddress((void**)&wch, g_wc_h);
    cudaGetSymbolAddress((void**)&wcl, g_wc_l);
    cudaGetSymbolAddress((void**)&qTh, g_qT_h);
    cudaGetSymbolAddress((void**)&qTl, g_qT_l);
    cudaGetSymbolAddress((void**)&qch, g_qcat_h);
    cudaGetSymbolAddress((void**)&qcl, g_qcat_l);
    cudaGetSymbolAddress((void**)&bch_, g_bcat_h);
    cudaGetSymbolAddress((void**)&bcl_, g_bcat_l);
    cudaGetSymbolAddress((void**)&fh, g_fss_h);
    cudaGetSymbolAddress((void**)&fl, g_fss_l);
    cudaGetSymbolAddress((void**)&cth, g_conqT_h);
    cudaGetSymbolAddress((void**)&ctl, g_conqT_l);
    cudaGetSymbolAddress((void**)&zp, g_z);
    cudaGetSymbolAddress((void**)&ccp, g_cc);

    // prep: weights split + query dual split + rule params
    {
        int n4 = (DD * DD) / 4;
        split_kernel<<<(n4 + 255) / 256, 256>>>(Wq, wqh, wql, n4);
        n4 = (RR * LL) / 4;
        split_kernel<<<(n4 + 255) / 256, 256>>>(Wc, wch, wcl, n4);
    }
    prep_kernel<<<RR, 128>>>(centers, widths);
    {
        dim3 g(LL / 32, DD / 32, BB);
        dim3 b(32, 8);
        query_prep_kernel<<<g, b>>>(query);
    }

    // G1: q = query @ Wq^T + bq -> qcat = [q^2 | q] split   (M=M1,N=D,K=D)
    {
        dim3 g(DD / 128, M1 / 128, 1);
        gemm_bf16s<0><<<g, 256, GEMM_SMEM>>>(qh, ql, DD, 0, wqh, wql, DD, 0,
                                             nullptr, nullptr, nullptr, 1024, 0, bq, DD);
    }
    // G2: z = scale * (qcat @ bcat^T + cc)   (M=M1,N=R,K=1024)
    {
        dim3 g(RR / 128, M1 / 128, 1);
        gemm_bf16s<1><<<g, 256, GEMM_SMEM>>>(qch, qcl, 1024, 0, bch_, bcl_, 1024, 0,
                                             zp, nullptr, nullptr, RR, 0, ccp, 1024);
    }
    softmax_kernel<<<M1, 256>>>();
    // G4: conqT[b] = qT[b] @ Wc^T + bc   (M=D, N=R, K=L, batched)
    {
        dim3 g(RR / 128, DD / 128, BB);
        gemm_bf16s<2><<<g, 256, GEMM_SMEM>>>(qTh, qTl, LL, (size_t)DD * LL,
                                             wch, wcl, LL, 0,
                                             nullptr, cth, ctl, RR, (size_t)DD * RR, bc, LL);
    }
    // G5: out[b] = Fss[b] @ conqT[b]^T   (M=L, N=D, K=R, batched)
    {
        dim3 g(DD / 128, LL / 128, BB);
        gemm_bf16s<3><<<g, 256, GEMM_SMEM>>>(fh, fl, RR, (size_t)LL * RR,
                                             cth, ctl, RR, (size_t)DD * RR,
                                             out, nullptr, nullptr, DD, (size_t)LL * DD,
                                             nullptr, RR);
    }
}

// round 8
// speedup vs baseline: 1.1540x; 1.1540x over previous
#include <cuda_runtime.h>
#include <cuda_bf16.h>
#include <cstdint>

// Problem constants
#define BB 8
#define LL 2048
#define DD 512
#define RR 512
#define M1 (BB * LL)   // 16384 flattened (B,L)

typedef __nv_bfloat16 bf16;
typedef __nv_bfloat162 bf162;

__device__ __forceinline__ uint32_t smem_to_u32(const void* smem_ptr) {
    uint32_t addr;
    asm("{ .reg .u64 tmp; cvta.to.shared.u64 tmp, %1; cvt.u32.u64 %0, tmp; }"
        : "=r"(addr) : "l"(smem_ptr));
    return addr;
}

__device__ __forceinline__ void bf16split(float x, bf16& h, bf16& l) {
    h = __float2bfloat16(x);
    l = __float2bfloat16(x - __bfloat162float(h));
}

#define CPASYNC16(dst, src) \
    asm volatile("cp.async.cg.shared.global [%0], [%1], 16;" :: "r"(dst), "l"(src))
#define CPASYNC_COMMIT() asm volatile("cp.async.commit_group;" ::: "memory")

#define LDSM4(r0, r1, r2, r3, addr) \
    asm volatile("ldmatrix.sync.aligned.m8n8.x4.shared.b16 {%0,%1,%2,%3}, [%4];" \
                 : "=r"(r0), "=r"(r1), "=r"(r2), "=r"(r3) : "r"(addr))

#define MMA16816(c, a, b) \
    asm volatile("mma.sync.aligned.m16n8k16.row.col.f32.bf16.bf16.f32 " \
                 "{%0,%1,%2,%3}, {%4,%5,%6,%7}, {%8,%9}, {%0,%1,%2,%3};" \
                 : "+f"((c)[0]), "+f"((c)[1]), "+f"((c)[2]), "+f"((c)[3]) \
                 : "r"((a)[0]), "r"((a)[1]), "r"((a)[2]), "r"((a)[3]), \
                   "r"((b)[0]), "r"((b)[1]))

// ---------------- scratch (device globals; no allocation allowed) ----------
__device__ bf16  g_query_h[(size_t)M1 * DD];
__device__ bf16  g_query_l[(size_t)M1 * DD];
__device__ bf16  g_wq_h[DD * DD];
__device__ bf16  g_wq_l[DD * DD];
__device__ bf16  g_wc_h[RR * LL];
__device__ bf16  g_wc_l[RR * LL];
__device__ bf16  g_qT_h[(size_t)BB * DD * LL];
__device__ bf16  g_qT_l[(size_t)BB * DD * LL];
__device__ bf16  g_qcat_h[(size_t)M1 * 1024];   // [q^2 | q]
__device__ bf16  g_qcat_l[(size_t)M1 * 1024];
__device__ bf16  g_bcat_h[RR * 1024];           // [invw2 | -2c*invw2]
__device__ bf16  g_bcat_l[RR * 1024];
__device__ float g_z[(size_t)M1 * RR];
__device__ bf16  g_fss_h[(size_t)M1 * RR];
__device__ bf16  g_fss_l[(size_t)M1 * RR];
__device__ bf16  g_conqT_h[(size_t)BB * DD * RR];
__device__ bf16  g_conqT_l[(size_t)BB * DD * RR];
__device__ float g_cc[RR];

// ---------------------------------------------------------------------------
// split: fp32 -> (hi, lo) bf16 (for Wq, Wc)
// ---------------------------------------------------------------------------
__global__ void split_kernel(const float* __restrict__ src, bf16* __restrict__ hi,
                             bf16* __restrict__ lo, int n4) {
    int i = blockIdx.x * blockDim.x + threadIdx.x;
    if (i >= n4) return;
    float4 v = ((const float4*)src)[i];
    bf16 h0, l0, h1, l1, h2, l2, h3, l3;
    bf16split(v.x, h0, l0); bf16split(v.y, h1, l1);
    bf16split(v.z, h2, l2); bf16split(v.w, h3, l3);
    bf162 hh0; hh0.x = h0; hh0.y = h1;
    bf162 hh1; hh1.x = h2; hh1.y = h3;
    bf162 ll0; ll0.x = l0; ll0.y = l1;
    bf162 ll1; ll1.x = l2; ll1.y = l3;
    ((bf162*)hi)[i * 2 + 0] = hh0;
    ((bf162*)hi)[i * 2 + 1] = hh1;
    ((bf162*)lo)[i * 2 + 0] = ll0;
    ((bf162*)lo)[i * 2 + 1] = ll1;
}

// ---------------------------------------------------------------------------
// query prep: single read of query -> row-major split AND transposed split
// ---------------------------------------------------------------------------
__global__ void query_prep_kernel(const float* __restrict__ query) {
    __shared__ float tile[32][33];
    int b = blockIdx.z;
    int l0 = blockIdx.x * 32, d0 = blockIdx.y * 32;
    int tx = threadIdx.x, ty = threadIdx.y;
    const float* src = query + (size_t)b * LL * DD;
#pragma unroll
    for (int i = 0; i < 4; i++) {
        int l = l0 + ty + 8 * i;
        float v = src[(size_t)l * DD + d0 + tx];
        tile[ty + 8 * i][tx] = v;
        bf16 h, lw;
        bf16split(v, h, lw);
        size_t idx = (size_t)(b * LL + l) * DD + d0 + tx;
        g_query_h[idx] = h;
        g_query_l[idx] = lw;
    }
    __syncthreads();
    size_t base = (size_t)b * DD * LL;
#pragma unroll
    for (int i = 0; i < 4; i++) {
        float v = tile[tx][ty + 8 * i];
        bf16 h, lw;
        bf16split(v, h, lw);
        size_t idx = base + (size_t)(d0 + ty + 8 * i) * LL + l0 + tx;
        g_qT_h[idx] = h;
        g_qT_l[idx] = lw;
    }
}

// ---------------------------------------------------------------------------
// prep: bcat = [invw2 | -2c*invw2] split, cc[r] = sum c^2*invw2
// ---------------------------------------------------------------------------
__global__ void prep_kernel(const float* __restrict__ centers,
                            const float* __restrict__ widths) {
    int r = blockIdx.x;
    int t = threadIdx.x;  // 128
    float acc = 0.f;
    for (int d = t; d < DD; d += 128) {
        float w = widths[r * DD + d];
        float c = centers[r * DD + d];
        float iw = 1.0f / (w * w);
        float b2 = -2.0f * c * iw;
        bf16 h, l;
        bf16split(iw, h, l);
        g_bcat_h[r * 1024 + d] = h;
        g_bcat_l[r * 1024 + d] = l;
        bf16split(b2, h, l);
        g_bcat_h[r * 1024 + 512 + d] = h;
        g_bcat_l[r * 1024 + 512 + d] = l;
        acc += c * c * iw;
    }
    __shared__ float sred[128];
    sred[t] = acc;
    __syncthreads();
    for (int s = 64; s > 0; s >>= 1) {
        if (t < s) sred[t] += sred[t + s];
        __syncthreads();
    }
    if (t == 0) g_cc[r] = sred[0];
}

// ---------------------------------------------------------------------------
// bf16-split NT GEMM via mma.sync m16n8k16, 3 passes (AhBh + AhBl + AlBh).
// 128x128 CTA tile, 8 warps of 64x32. K-chunk 64, 2-stage cp.async pipeline.
// SMEM tile: 128 rows x 128B data, 144B pitch (conflict-free ldmatrix+store).
// MODE 0: qcat ((v+aux)^2 | (v+aux), split; ldc=1024)
// MODE 1: fp32 scale*(v+aux[n]) -> Cf
// MODE 2: split bf16 v+aux[n]   -> Ch/Cl
// MODE 3: fp32 raw              -> Cf
// ---------------------------------------------------------------------------
#define TPITCH 144
#define TILE_B (128 * TPITCH)        // 18432
#define STAGE_B (4 * TILE_B)         // 73728: Ah, Al, Bh, Bl
#define GEMM_SMEM (2 * STAGE_B)      // 147456

template <int MODE>
__global__ __launch_bounds__(256, 1) void gemm_bf16s(
    const bf16* __restrict__ Ah, const bf16* __restrict__ Al, int lda, size_t sA,
    const bf16* __restrict__ Bh, const bf16* __restrict__ Bl, int ldb, size_t sB,
    float* __restrict__ Cf, bf16* __restrict__ Ch, bf16* __restrict__ Cl,
    int ldc, size_t sC, const float* __restrict__ aux, int K) {
    extern __shared__ char smem[];
    uint32_t sb = smem_to_u32(smem);
    int t = threadIdx.x;
    int lane = t & 31, wid = t >> 5;
    int wm = wid & 1, wn = wid >> 1;
    int bn = blockIdx.x * 128, bm = blockIdx.y * 128;
    size_t bz = blockIdx.z;
    Ah += bz * sA; Al += bz * sA;
    Bh += bz * sB; Bl += bz * sB;

    // cp.async plan: each thread does 16 x 16B per 64-wide K-chunk.
    // r0 = t>>3 (0..31), c = t&7 (16B column). Rows r0 + 32*i, i=0..3.
    int r0 = t >> 3;
    int cc = t & 7;
    const bf16* gA_h = Ah + (size_t)(bm + r0) * lda + cc * 8;
    const bf16* gA_l = Al + (size_t)(bm + r0) * lda + cc * 8;
    const bf16* gB_h = Bh + (size_t)(bn + r0) * ldb + cc * 8;
    const bf16* gB_l = Bl + (size_t)(bn + r0) * ldb + cc * 8;
    uint32_t soff = (uint32_t)(r0 * TPITCH + cc * 16);

    float acc[4][4][4] = {};
    const int nk = K >> 6;

    // prologue: chunk 0 -> stage 0
    {
        uint32_t db = sb;
#pragma unroll
        for (int i = 0; i < 4; i++) {
            uint32_t o = soff + (uint32_t)(i * 32 * TPITCH);
            size_t ga = (size_t)(32 * i) * lda;
            size_t gb = (size_t)(32 * i) * ldb;
            CPASYNC16(db + o,              gA_h + ga);
            CPASYNC16(db + TILE_B + o,     gA_l + ga);
            CPASYNC16(db + 2 * TILE_B + o, gB_h + gb);
            CPASYNC16(db + 3 * TILE_B + o, gB_l + gb);
        }
        CPASYNC_COMMIT();
    }

    int lm = lane & 15, lq = lane >> 4;
    uint32_t a_base = (uint32_t)((wm * 64 + lm) * TPITCH);
    uint32_t b_base = (uint32_t)((wn * 32 + lm) * TPITCH);

    for (int kt = 0; kt < nk; kt++) {
        int buf = kt & 1;
        if (kt + 1 < nk) {
            uint32_t db = sb + (buf ^ 1) * STAGE_B;
            int koff = (kt + 1) * 64;
#pragma unroll
            for (int i = 0; i < 4; i++) {
                uint32_t o = soff + (uint32_t)(i * 32 * TPITCH);
                size_t ga = (size_t)(32 * i) * lda + koff;
                size_t gb = (size_t)(32 * i) * ldb + koff;
                CPASYNC16(db + o,              gA_h + ga);
                CPASYNC16(db + TILE_B + o,     gA_l + ga);
                CPASYNC16(db + 2 * TILE_B + o, gB_h + gb);
                CPASYNC16(db + 3 * TILE_B + o, gB_l + gb);
            }
            CPASYNC_COMMIT();
            asm volatile("cp.async.wait_group 1;" ::: "memory");
        } else {
            asm volatile("cp.async.wait_group 0;" ::: "memory");
        }
        __syncthreads();
        uint32_t base = sb + buf * STAGE_B;
#pragma unroll
        for (int ks = 0; ks < 4; ks++) {
            uint32_t off16 = (uint32_t)((2 * ks + lq) * 16);
            uint32_t a[4][4], bh[4][2], bl[4][2];
#pragma unroll
            for (int i = 0; i < 4; i++)
                LDSM4(a[i][0], a[i][1], a[i][2], a[i][3],
                      base + a_base + i * (16 * TPITCH) + off16);
#pragma unroll
            for (int jj = 0; jj < 2; jj++) {
                uint32_t q0, q1, q2, q3;
                LDSM4(q0, q1, q2, q3,
                      base + 2 * TILE_B + b_base + jj * (16 * TPITCH) + off16);
                bh[2 * jj][0] = q0; bh[2 * jj][1] = q2;
                bh[2 * jj + 1][0] = q1; bh[2 * jj + 1][1] = q3;
            }
#pragma unroll
            for (int i = 0; i < 4; i++)
#pragma unroll
                for (int j = 0; j < 4; j++) MMA16816(acc[i][j], a[i], bh[j]);
#pragma unroll
            for (int jj = 0; jj < 2; jj++) {
                uint32_t q0, q1, q2, q3;
                LDSM4(q0, q1, q2, q3,
                      base + 3 * TILE_B + b_base + jj * (16 * TPITCH) + off16);
                bl[2 * jj][0] = q0; bl[2 * jj][1] = q2;
                bl[2 * jj + 1][0] = q1; bl[2 * jj + 1][1] = q3;
            }
#pragma unroll
            for (int i = 0; i < 4; i++)
#pragma unroll
                for (int j = 0; j < 4; j++) MMA16816(acc[i][j], a[i], bl[j]);
#pragma unroll
            for (int i = 0; i < 4; i++)
                LDSM4(a[i][0], a[i][1], a[i][2], a[i][3],
                      base + TILE_B + a_base + i * (16 * TPITCH) + off16);
#pragma unroll
            for (int i = 0; i < 4; i++)
#pragma unroll
                for (int j = 0; j < 4; j++) MMA16816(acc[i][j], a[i], bh[j]);
        }
        __syncthreads();
    }

    // epilogue (register-direct, as in the 575us version)
    int rbase = bm + wm * 64 + (lane >> 2);
    int nbase = bn + wn * 32 + (lane & 3) * 2;
#pragma unroll
    for (int i = 0; i < 4; i++) {
#pragma unroll
        for (int j = 0; j < 4; j++) {
            int n = nbase + j * 8;
#pragma unroll
            for (int h = 0; h < 2; h++) {
                int m = rbase + i * 16 + h * 8;
                float v0 = acc[i][j][2 * h];
                float v1 = acc[i][j][2 * h + 1];
                if (MODE == 0) {
                    size_t crow = (size_t)m * ldc;
                    float q0 = v0 + aux[n], q1 = v1 + aux[n + 1];
                    bf16 h0, l0, h1, l1;
                    bf16split(q0 * q0, h0, l0); bf16split(q1 * q1, h1, l1);
                    bf162 hh; hh.x = h0; hh.y = h1;
                    bf162 ll; ll.x = l0; ll.y = l1;
                    *(bf162*)(Ch + crow + n) = hh;
                    *(bf162*)(Cl + crow + n) = ll;
                    bf16split(q0, h0, l0); bf16split(q1, h1, l1);
                    hh.x = h0; hh.y = h1; ll.x = l0; ll.y = l1;
                    *(bf162*)(Ch + crow + 512 + n) = hh;
                    *(bf162*)(Cl + crow + 512 + n) = ll;
                } else if (MODE == 1) {
                    const float scale = -0.5f / (float)DD;
                    size_t crow = (size_t)m * ldc;
                    float2 o;
                    o.x = scale * (v0 + aux[n]);
                    o.y = scale * (v1 + aux[n + 1]);
                    *(float2*)(Cf + crow + n) = o;
                } else if (MODE == 2) {
                    size_t crow = bz * sC + (size_t)m * ldc;
                    float q0 = v0 + aux[n], q1 = v1 + aux[n + 1];
                    bf16 h0, l0, h1, l1;
                    bf16split(q0, h0, l0); bf16split(q1, h1, l1);
                    bf162 hh; hh.x = h0; hh.y = h1;
                    bf162 ll; ll.x = l0; ll.y = l1;
                    *(bf162*)(Ch + crow + n) = hh;
                    *(bf162*)(Cl + crow + n) = ll;
                } else {
                    size_t crow = bz * sC + (size_t)m * ldc;
                    float2 o; o.x = v0; o.y = v1;
                    *(float2*)(Cf + crow + n) = o;
                }
            }
        }
    }
}

// ---------------------------------------------------------------------------
// softmax over R: reads fp32 g_z (scaled logits), writes split Fss
// ---------------------------------------------------------------------------
__global__ void softmax_kernel() {
    int row = blockIdx.x;
    int t = threadIdx.x;  // 256
    const float* zrow = g_z + (size_t)row * RR;
    float v0 = zrow[t];
    float v1 = zrow[t + 256];
    float m = fmaxf(v0, v1);
#pragma unroll
    for (int o = 16; o > 0; o >>= 1) m = fmaxf(m, __shfl_xor_sync(0xffffffffu, m, o));
    __shared__ float sm[8];
    __shared__ float ss[8];
    int wid = t >> 5, lid = t & 31;
    if (lid == 0) sm[wid] = m;
    __syncthreads();
    float mm = sm[0];
#pragma unroll
    for (int i = 1; i < 8; i++) mm = fmaxf(mm, sm[i]);
    float e0 = __expf(v0 - mm), e1 = __expf(v1 - mm);
    float s = e0 + e1;
#pragma unroll
    for (int o = 16; o > 0; o >>= 1) s += __shfl_xor_sync(0xffffffffu, s, o);
    if (lid == 0) ss[wid] = s;
    __syncthreads();
    float tot = 0.f;
#pragma unroll
    for (int i = 0; i < 8; i++) tot += ss[i];
    float inv = 1.0f / tot;
    size_t i0 = (size_t)row * RR + t;
    size_t i1 = i0 + 256;
    bf16 h, l;
    bf16split(e0 * inv, h, l);
    g_fss_h[i0] = h; g_fss_l[i0] = l;
    bf16split(e1 * inv, h, l);
    g_fss_h[i1] = h; g_fss_l[i1] = l;
}

// ---------------------------------------------------------------------------
extern "C" void kernel_launch(void* const* d_in, const int* in_sizes, int n_in,
                              void* d_out, int out_size) {
    const float* query   = (const float*)d_in[0];   // (B,L,D)
    const float* Wq      = (const float*)d_in[1];   // (D,D)
    const float* bq      = (const float*)d_in[2];   // (D,)
    const float* Wc      = (const float*)d_in[3];   // (R,L)
    const float* bc      = (const float*)d_in[4];   // (R,)
    const float* centers = (const float*)d_in[5];   // (R,D)
    const float* widths  = (const float*)d_in[6];   // (R,D)
    float* out = (float*)d_out;                     // (B,L,D)

    cudaFuncSetAttribute(gemm_bf16s<0>, cudaFuncAttributeMaxDynamicSharedMemorySize, GEMM_SMEM);
    cudaFuncSetAttribute(gemm_bf16s<1>, cudaFuncAttributeMaxDynamicSharedMemorySize, GEMM_SMEM);
    cudaFuncSetAttribute(gemm_bf16s<2>, cudaFuncAttributeMaxDynamicSharedMemorySize, GEMM_SMEM);
    cudaFuncSetAttribute(gemm_bf16s<3>, cudaFuncAttributeMaxDynamicSharedMemorySize, GEMM_SMEM);

    bf16 *qh, *ql, *wqh, *wql, *wch, *wcl, *qTh, *qTl, *qch, *qcl;
    bf16 *bch_, *bcl_, *fh, *fl, *cth, *ctl;
    float *zp, *ccp;
    cudaGetSymbolAddress((void**)&qh, g_query_h);
    cudaGetSymbolAddress((void**)&ql, g_query_l);
    cudaGetSymbolAddress((void**)&wqh, g_wq_h);
    cudaGetSymbolAddress((void**)&wql, g_wq_l);
    cudaGetSymbolAddress((void**)&wch, g_wc_h);
    cudaGetSymbolAddress((void**)&wcl, g_wc_l);
    cudaGetSymbolAddress((void**)&qTh, g_qT_h);
    cudaGetSymbolAddress((void**)&qTl, g_qT_l);
    cudaGetSymbolAddress((void**)&qch, g_qcat_h);
    cudaGetSymbolAddress((void**)&qcl, g_qcat_l);
    cudaGetSymbolAddress((void**)&bch_, g_bcat_h);
    cudaGetSymbolAddress((void**)&bcl_, g_bcat_l);
    cudaGetSymbolAddress((void**)&fh, g_fss_h);
    cudaGetSymbolAddress((void**)&fl, g_fss_l);
    cudaGetSymbolAddress((void**)&cth, g_conqT_h);
    cudaGetSymbolAddress((void**)&ctl, g_conqT_l);
    cudaGetSymbolAddress((void**)&zp, g_z);
    cudaGetSymbolAddress((void**)&ccp, g_cc);

    // prep: weights split + query dual split + rule params
    {
        int n4 = (DD * DD) / 4;
        split_kernel<<<(n4 + 255) / 256, 256>>>(Wq, wqh, wql, n4);
        n4 = (RR * LL) / 4;
        split_kernel<<<(n4 + 255) / 256, 256>>>(Wc, wch, wcl, n4);
    }
    prep_kernel<<<RR, 128>>>(centers, widths);
    {
        dim3 g(LL / 32, DD / 32, BB);
        dim3 b(32, 8);
        query_prep_kernel<<<g, b>>>(query);
    }

    // G1: q = query @ Wq^T + bq -> qcat = [q^2 | q] split   (M=M1,N=D,K=D)
    {
        dim3 g(DD / 128, M1 / 128, 1);
        gemm_bf16s<0><<<g, 256, GEMM_SMEM>>>(qh, ql, DD, 0, wqh, wql, DD, 0,
                                             nullptr, qch, qcl, 1024, 0, bq, DD);
    }
    // G2: z = scale * (qcat @ bcat^T + cc)   (M=M1,N=R,K=1024)
    {
        dim3 g(RR / 128, M1 / 128, 1);
        gemm_bf16s<1><<<g, 256, GEMM_SMEM>>>(qch, qcl, 1024, 0, bch_, bcl_, 1024, 0,
                                             zp, nullptr, nullptr, RR, 0, ccp, 1024);
    }
    softmax_kernel<<<M1, 256>>>();
    // G4: conqT[b] = qT[b] @ Wc^T + bc   (M=D, N=R, K=L, batched)
    {
        dim3 g(RR / 128, DD / 128, BB);
        gemm_bf16s<2><<<g, 256, GEMM_SMEM>>>(qTh, qTl, LL, (size_t)DD * LL,
                                             wch, wcl, LL, 0,
                                             nullptr, cth, ctl, RR, (size_t)DD * RR, bc, LL);
    }
    // G5: out[b] = Fss[b] @ conqT[b]^T   (M=L, N=D, K=R, batched)
    {
        dim3 g(DD / 128, LL / 128, BB);
        gemm_bf16s<3><<<g, 256, GEMM_SMEM>>>(fh, fl, RR, (size_t)LL * RR,
                                             cth, ctl, RR, (size_t)DD * RR,
                                             out, nullptr, nullptr, DD, (size_t)LL * DD,
                                             nullptr, RR);
    }
}